// round 1
// baseline (speedup 1.0000x reference)
#include <cuda_runtime.h>
#include <math.h>

#define NN  50000
#define EE  800000
#define ET  850000   // EE + NN self loops
#define HD  128

// ---------------- scratch (device globals; no allocation allowed) ----------------
__device__ float g_h[NN*HD];
__device__ float g_xl0[NN*HD];
__device__ float g_xr0[NN*HD];
__device__ float g_xl1[NN*HD];
__device__ float g_xr1[NN*HD];
__device__ float g_aggA[NN*HD];
__device__ float g_aggB[NN*HD];
__device__ float g_z[NN*256];
__device__ float g_tmp[NN*HD];
__device__ float g_invn[4*NN];
__device__ float g_xaux[NN];
__device__ float g_bvec[256];
__device__ float g_bnstat[256];       // sum[0:128], sumsq[128:256]
__device__ int   g_deg_in[NN];
__device__ int   g_deg_out[NN];
__device__ int   g_off_in[NN+1];
__device__ int   g_off_out[NN+1];
__device__ int   g_cur_in[NN];
__device__ int   g_cur_out[NN];
__device__ int   g_col_in[ET];
__device__ int   g_col_out[ET];

// ---------------- helpers ----------------
__device__ __forceinline__ float gelu_f(float x) {
    return 0.5f * x * (1.0f + erff(x * 0.70710678118654752f));
}

// ---------------- tiny utility kernels ----------------
__global__ void zero_int_kernel(int* p, int n) {
    int i = blockIdx.x * blockDim.x + threadIdx.x;
    if (i < n) p[i] = 0;
}
__global__ void zero_float_kernel(float* p, int n) {
    int i = blockIdx.x * blockDim.x + threadIdx.x;
    if (i < n) p[i] = 0.0f;
}

__global__ void aux_kernel(const float* __restrict__ aux, const float* __restrict__ c,
                           const float* __restrict__ d, float* __restrict__ out) {
    int i = blockIdx.x * blockDim.x + threadIdx.x;
    if (i < NN) {
        float v = c[0] * aux[i] - d[0];
        out[i] = 1.0f / (1.0f + __expf(-v));
    }
}

__global__ void hist_kernel(const int* __restrict__ ei, int* __restrict__ din,
                            int* __restrict__ dout) {
    int e = blockIdx.x * blockDim.x + threadIdx.x;
    if (e >= EE) return;
    int s = ei[e];
    int d = ei[EE + e];
    atomicAdd(&dout[s], 1);
    atomicAdd(&din[d], 1);
}

// single-block inclusive scan over (deg[i]+1); writes row offsets, places the
// canonical self loop at the segment head, and initializes the scatter cursor.
__global__ void scan_kernel(const int* __restrict__ deg, int* __restrict__ roff,
                            int* __restrict__ cursor, int* __restrict__ colidx) {
    __shared__ int sh[1024];
    int carry = 0;
    if (threadIdx.x == 0) roff[0] = 0;
    for (int base = 0; base < NN; base += 1024) {
        int i = base + threadIdx.x;
        int v = (i < NN) ? (deg[i] + 1) : 0;
        sh[threadIdx.x] = v;
        __syncthreads();
        #pragma unroll
        for (int off = 1; off < 1024; off <<= 1) {
            int t = (threadIdx.x >= off) ? sh[threadIdx.x - off] : 0;
            __syncthreads();
            sh[threadIdx.x] += t;
            __syncthreads();
        }
        if (i < NN) {
            int incl = carry + sh[threadIdx.x];
            int ex   = incl - v;
            roff[i + 1] = incl;
            colidx[ex]  = i;       // self loop first
            cursor[i]   = ex + 1;
        }
        carry += sh[1023];
        __syncthreads();
    }
}

__global__ void scatter_kernel(const int* __restrict__ ei, int* __restrict__ cin,
                               int* __restrict__ colin, int* __restrict__ cout,
                               int* __restrict__ colout) {
    int e = blockIdx.x * blockDim.x + threadIdx.x;
    if (e >= EE) return;
    int s = ei[e];
    int d = ei[EE + e];
    int p = atomicAdd(&cin[d], 1);  colin[p]  = s;
    int q = atomicAdd(&cout[s], 1); colout[q] = d;
}

// ---------------- batchnorm ----------------
__global__ void bn_reduce_kernel(const float* __restrict__ h, float* __restrict__ stat) {
    int col = threadIdx.x;   // 128 threads
    float s = 0.f, ss = 0.f;
    for (int r = blockIdx.x; r < NN; r += gridDim.x) {
        float v = h[(size_t)r * HD + col];
        s += v; ss += v * v;
    }
    atomicAdd(&stat[col], s);
    atomicAdd(&stat[128 + col], ss);
}

__global__ void bn_apply_kernel(float* __restrict__ h, const float* __restrict__ stat,
                                const float* __restrict__ gamma, const float* __restrict__ beta) {
    int idx = blockIdx.x * blockDim.x + threadIdx.x;
    if (idx >= NN * HD) return;
    int col = idx & (HD - 1);
    const float invN = 1.0f / (float)NN;
    float mu  = stat[col] * invN;
    float var = stat[128 + col] * invN - mu * mu;
    float v = h[idx];
    h[idx] = (v - mu) * rsqrtf(var + 1e-5f) * gamma[col] + beta[col];
}

// ---------------- row inverse-norm ----------------
__global__ void invnorm_kernel(const float* __restrict__ x, float* __restrict__ invn) {
    int w = (blockIdx.x * blockDim.x + threadIdx.x) >> 5;
    int lane = threadIdx.x & 31;
    if (w >= NN) return;
    float4 v = *(const float4*)&x[(size_t)w * HD + lane * 4];
    float ss = v.x * v.x + v.y * v.y + v.z * v.z + v.w * v.w;
    ss += __shfl_xor_sync(0xffffffffu, ss, 16);
    ss += __shfl_xor_sync(0xffffffffu, ss, 8);
    ss += __shfl_xor_sync(0xffffffffu, ss, 4);
    ss += __shfl_xor_sync(0xffffffffu, ss, 2);
    ss += __shfl_xor_sync(0xffffffffu, ss, 1);
    if (lane == 0) invn[w] = 1.0f / fmaxf(sqrtf(ss), 1e-12f);
}

// ---------------- bias @ wcat fold (both directions of one layer) ----------------
__global__ void bvec_kernel(const float* __restrict__ bias, const float* __restrict__ wcat,
                            float* __restrict__ bvec) {
    int tid = threadIdx.x;                // 256 threads: dir = tid>>7
    int dir = tid >> 7, t = tid & 127;
    const float* b = bias + dir * 128;
    const float* w = wcat + dir * 128 * 128;
    float acc = 0.f;
    for (int k = 0; k < 128; ++k) acc += b[k] * w[k * 128 + t];
    bvec[tid] = acc;
}

// ---------------- GAT-COS single-pass aggregation (warp per target node) -------
// alpha_raw = x_aux[j] * |dot(xr_i, xl_j)| * invnr_i * invnl_j / 0.25  (>= 0, <= ~0.84)
// softmax needs no max-subtraction; exp is stable. One gather of xl[j] per edge.
__global__ void gat_kernel(const int* __restrict__ roff, const int* __restrict__ col,
                           const float* __restrict__ xl, const float* __restrict__ xr,
                           const float* __restrict__ invl, const float* __restrict__ invr,
                           const float* __restrict__ xaux, float* __restrict__ agg) {
    int w = (blockIdx.x * blockDim.x + threadIdx.x) >> 5;
    int lane = threadIdx.x & 31;
    if (w >= NN) return;
    float inr = invr[w];
    float4 xri = *(const float4*)&xr[(size_t)w * HD + lane * 4];
    float4 nr = make_float4(xri.x * inr, xri.y * inr, xri.z * inr, xri.w * inr);
    float s = 0.f;
    float4 acc = make_float4(0.f, 0.f, 0.f, 0.f);
    int e0 = roff[w], e1 = roff[w + 1];
    for (int e = e0; e < e1; ++e) {
        int j = col[e];
        float4 xj = *(const float4*)&xl[(size_t)j * HD + lane * 4];
        float p = nr.x * xj.x + nr.y * xj.y + nr.z * xj.z + nr.w * xj.w;
        p += __shfl_xor_sync(0xffffffffu, p, 16);
        p += __shfl_xor_sync(0xffffffffu, p, 8);
        p += __shfl_xor_sync(0xffffffffu, p, 4);
        p += __shfl_xor_sync(0xffffffffu, p, 2);
        p += __shfl_xor_sync(0xffffffffu, p, 1);
        float a  = xaux[j] * fabsf(p) * invl[j] * 4.0f;
        float ee = __expf(a);
        s += ee;
        acc.x += ee * xj.x; acc.y += ee * xj.y;
        acc.z += ee * xj.z; acc.w += ee * xj.w;
    }
    float is = 1.0f / s;
    float4 o = make_float4(acc.x * is, acc.y * is, acc.z * is, acc.w * is);
    *(float4*)&agg[(size_t)w * HD + lane * 4] = o;
}

// ---------------- fp32 SGEMM: C = A(MxK) @ B(KxN) (+bias) (+gelu) ----------------
// BM=BN=128, BK=8, 256 threads, 8x8 micro-tile per thread.
template <bool GELU>
__global__ __launch_bounds__(256)
void sgemm_kernel(const float* __restrict__ A, const float* __restrict__ B,
                  float* __restrict__ C, const float* __restrict__ bias,
                  int M, int N, int K, int lda, int ldb, int ldc) {
    const int BM = 128, BN = 128, BK = 8;
    __shared__ float As[BK][BM];
    __shared__ float Bs[BK][BN];
    int tid = threadIdx.x;
    int row0 = blockIdx.y * BM;
    int col0 = blockIdx.x * BN;

    int arow = tid >> 1;            // 0..127
    int acol = (tid & 1) * 4;       // 0 or 4
    int brow = tid >> 5;            // 0..7
    int bcol = (tid & 31) * 4;      // 0..124
    int tx = tid & 15, ty = tid >> 4;

    float acc[8][8];
    #pragma unroll
    for (int i = 0; i < 8; ++i)
        #pragma unroll
        for (int j = 0; j < 8; ++j) acc[i][j] = 0.f;

    int nIter = K / BK;
    for (int t = 0; t < nIter; ++t) {
        int k0 = t * BK;
        float4 a4;
        int ar = row0 + arow;
        if (ar < M) a4 = *(const float4*)&A[(size_t)ar * lda + k0 + acol];
        else        a4 = make_float4(0.f, 0.f, 0.f, 0.f);
        As[acol + 0][arow] = a4.x;
        As[acol + 1][arow] = a4.y;
        As[acol + 2][arow] = a4.z;
        As[acol + 3][arow] = a4.w;
        float4 b4 = *(const float4*)&B[(size_t)(k0 + brow) * ldb + col0 + bcol];
        *(float4*)&Bs[brow][bcol] = b4;
        __syncthreads();
        #pragma unroll
        for (int kk = 0; kk < BK; ++kk) {
            float ra[8], rb[8];
            *(float4*)&ra[0] = *(const float4*)&As[kk][ty * 8];
            *(float4*)&ra[4] = *(const float4*)&As[kk][ty * 8 + 4];
            *(float4*)&rb[0] = *(const float4*)&Bs[kk][tx * 8];
            *(float4*)&rb[4] = *(const float4*)&Bs[kk][tx * 8 + 4];
            #pragma unroll
            for (int i = 0; i < 8; ++i)
                #pragma unroll
                for (int j = 0; j < 8; ++j) acc[i][j] += ra[i] * rb[j];
        }
        __syncthreads();
    }

    #pragma unroll
    for (int i = 0; i < 8; ++i) {
        int r = row0 + ty * 8 + i;
        if (r >= M) continue;
        #pragma unroll
        for (int j = 0; j < 8; j += 4) {
            int cb = col0 + tx * 8 + j;
            float4 v = make_float4(acc[i][j], acc[i][j+1], acc[i][j+2], acc[i][j+3]);
            if (bias) {
                v.x += bias[cb];     v.y += bias[cb + 1];
                v.z += bias[cb + 2]; v.w += bias[cb + 3];
            }
            if (GELU) {
                v.x = gelu_f(v.x); v.y = gelu_f(v.y);
                v.z = gelu_f(v.z); v.w = gelu_f(v.w);
            }
            *(float4*)&C[(size_t)r * ldc + cb] = v;
        }
    }
}

// ---------------- host ----------------
static void* sym(const void* s) {
    void* p = nullptr;
    cudaGetSymbolAddress(&p, s);
    return p;
}

extern "C" void kernel_launch(void* const* d_in, const int* in_sizes, int n_in,
                              void* d_out, int out_size) {
    const float* x      = (const float*)d_in[0];
    const int*   ei     = (const int*)  d_in[1];
    const float* nsa    = (const float*)d_in[2];
    const float* c_p    = (const float*)d_in[3];
    const float* d_p    = (const float*)d_in[4];
    const float* w_in   = (const float*)d_in[5];
    const float* b_in   = (const float*)d_in[6];
    const float* bn_g   = (const float*)d_in[7];
    const float* bn_b   = (const float*)d_in[8];
    const float* lin_l  = (const float*)d_in[9];
    const float* lin_r  = (const float*)d_in[10];
    const float* attb   = (const float*)d_in[11];
    const float* wcat   = (const float*)d_in[12];
    const float* ffw1   = (const float*)d_in[13];
    const float* ffb1   = (const float*)d_in[14];
    const float* ffw2   = (const float*)d_in[15];
    const float* ffb2   = (const float*)d_in[16];
    const float* wproj  = (const float*)d_in[17];
    const float* bproj  = (const float*)d_in[18];
    float* out = (float*)d_out;

    float* p_h    = (float*)sym(g_h);
    float* p_xl0  = (float*)sym(g_xl0);
    float* p_xr0  = (float*)sym(g_xr0);
    float* p_xl1  = (float*)sym(g_xl1);
    float* p_xr1  = (float*)sym(g_xr1);
    float* p_aggA = (float*)sym(g_aggA);
    float* p_aggB = (float*)sym(g_aggB);
    float* p_z    = (float*)sym(g_z);
    float* p_tmp  = (float*)sym(g_tmp);
    float* p_invn = (float*)sym(g_invn);
    float* p_xaux = (float*)sym(g_xaux);
    float* p_bvec = (float*)sym(g_bvec);
    float* p_bn   = (float*)sym(g_bnstat);
    int* p_din  = (int*)sym(g_deg_in);
    int* p_dout = (int*)sym(g_deg_out);
    int* p_oin  = (int*)sym(g_off_in);
    int* p_oout = (int*)sym(g_off_out);
    int* p_cin  = (int*)sym(g_cur_in);
    int* p_cout = (int*)sym(g_cur_out);
    int* p_colin  = (int*)sym(g_col_in);
    int* p_colout = (int*)sym(g_col_out);

    // ---- gating + CSR build ----
    aux_kernel<<<(NN + 255) / 256, 256>>>(nsa, c_p, d_p, p_xaux);
    zero_int_kernel<<<(NN + 255) / 256, 256>>>(p_din, NN);
    zero_int_kernel<<<(NN + 255) / 256, 256>>>(p_dout, NN);
    hist_kernel<<<(EE + 255) / 256, 256>>>(ei, p_din, p_dout);
    scan_kernel<<<1, 1024>>>(p_din, p_oin, p_cin, p_colin);
    scan_kernel<<<1, 1024>>>(p_dout, p_oout, p_cout, p_colout);
    scatter_kernel<<<(EE + 255) / 256, 256>>>(ei, p_cin, p_colin, p_cout, p_colout);

    const int MB = (NN + 127) / 128;   // 391
    dim3 g128(1, MB), g512(4, MB);
    const int gatBlocks = (NN * 32 + 255) / 256;

    // ---- input projection ----
    sgemm_kernel<false><<<g128, 256>>>(x, w_in, p_h, b_in, NN, HD, 256, 256, HD, HD);

    for (int l = 0; l < 2; ++l) {
        // batchnorm (in place)
        zero_float_kernel<<<1, 256>>>(p_bn, 256);
        bn_reduce_kernel<<<512, 128>>>(p_h, p_bn);
        bn_apply_kernel<<<(NN * HD + 255) / 256, 256>>>(p_h, p_bn, bn_g + l * HD, bn_b + l * HD);

        // per-direction linear projections
        const float* wl0 = lin_l + (size_t)(l * 2 + 0) * HD * HD;
        const float* wl1 = lin_l + (size_t)(l * 2 + 1) * HD * HD;
        const float* wr0 = lin_r + (size_t)(l * 2 + 0) * HD * HD;
        const float* wr1 = lin_r + (size_t)(l * 2 + 1) * HD * HD;
        sgemm_kernel<false><<<g128, 256>>>(p_h, wl0, p_xl0, nullptr, NN, HD, HD, HD, HD, HD);
        sgemm_kernel<false><<<g128, 256>>>(p_h, wr0, p_xr0, nullptr, NN, HD, HD, HD, HD, HD);
        sgemm_kernel<false><<<g128, 256>>>(p_h, wl1, p_xl1, nullptr, NN, HD, HD, HD, HD, HD);
        sgemm_kernel<false><<<g128, 256>>>(p_h, wr1, p_xr1, nullptr, NN, HD, HD, HD, HD, HD);

        invnorm_kernel<<<gatBlocks, 256>>>(p_xl0, p_invn + 0 * NN);
        invnorm_kernel<<<gatBlocks, 256>>>(p_xr0, p_invn + 1 * NN);
        invnorm_kernel<<<gatBlocks, 256>>>(p_xl1, p_invn + 2 * NN);
        invnorm_kernel<<<gatBlocks, 256>>>(p_xr1, p_invn + 3 * NN);

        // fold attention bias through wcat
        bvec_kernel<<<1, 256>>>(attb + (size_t)l * 256, wcat + (size_t)l * 2 * HD * HD, p_bvec);

        // direction 0: messages src->dst (group by dst)
        gat_kernel<<<gatBlocks, 256>>>(p_oin, p_colin, p_xl0, p_xr0,
                                       p_invn + 0 * NN, p_invn + 1 * NN, p_xaux, p_aggA);
        // direction 1: messages dst->src (group by src)
        gat_kernel<<<gatBlocks, 256>>>(p_oout, p_colout, p_xl1, p_xr1,
                                       p_invn + 2 * NN, p_invn + 3 * NN, p_xaux, p_aggB);

        // z = [gelu(aggA@wcat0 + b0) | gelu(aggB@wcat1 + b1)]
        const float* wc0 = wcat + (size_t)(l * 2 + 0) * HD * HD;
        const float* wc1 = wcat + (size_t)(l * 2 + 1) * HD * HD;
        sgemm_kernel<true><<<g128, 256>>>(p_aggA, wc0, p_z,       p_bvec,       NN, HD, HD, HD, HD, 256);
        sgemm_kernel<true><<<g128, 256>>>(p_aggB, wc1, p_z + 128, p_bvec + 128, NN, HD, HD, HD, HD, 256);

        // ffn
        sgemm_kernel<true ><<<g128, 256>>>(p_z,   ffw1 + (size_t)l * 256 * HD, p_tmp, ffb1 + l * HD,
                                           NN, HD, 256, 256, HD, HD);
        sgemm_kernel<false><<<g128, 256>>>(p_tmp, ffw2 + (size_t)l * HD * HD, p_h, ffb2 + l * HD,
                                           NN, HD, HD, HD, HD, HD);
    }

    // final projection -> d_out [NN, 512]
    sgemm_kernel<false><<<g512, 256>>>(p_h, wproj, out, bproj, NN, 512, HD, HD, 512, 512);
}

// round 3
// speedup vs baseline: 1.3847x; 1.3847x over previous
#include <cuda_runtime.h>
#include <cuda_bf16.h>
#include <cstdint>
#include <math.h>

#define NN  50000
#define EE  800000
#define ET  850000
#define HD  128

// ---------------- weight-transpose offsets (elements) ----------------
#define OFF_WIN 0
#define OFF_LL  32768
#define OFF_LR  98304
#define OFF_WC  163840
#define OFF_F1  229376
#define OFF_F2  294912
#define OFF_PJ  327680
#define WTOT    393216

// ---------------- device scratch ----------------
__device__ float g_h[NN*HD];
__device__ float g_xl0[NN*HD];
__device__ float g_xr0[NN*HD];
__device__ float g_xl1[NN*HD];
__device__ float g_xr1[NN*HD];
__device__ float g_invn[4*NN];
__device__ float g_xaux[NN];
__device__ float g_bvec[256];
__device__ float g_bnstat[256];
__device__ int   g_deg_in[NN];
__device__ int   g_deg_out[NN];
__device__ int   g_off_in[NN+1];
__device__ int   g_off_out[NN+1];
__device__ int   g_cur_in[NN];
__device__ int   g_cur_out[NN];
__device__ int   g_col_in[ET];
__device__ int   g_col_out[ET];
// bf16 hi/lo operand buffers
__device__ __nv_bfloat16 g_xh [NN*256];
__device__ __nv_bfloat16 g_xlo[NN*256];
__device__ __nv_bfloat16 g_hh [NN*HD];
__device__ __nv_bfloat16 g_hl [NN*HD];
__device__ __nv_bfloat16 g_aAh[NN*HD];
__device__ __nv_bfloat16 g_aAl[NN*HD];
__device__ __nv_bfloat16 g_aBh[NN*HD];
__device__ __nv_bfloat16 g_aBl[NN*HD];
__device__ __nv_bfloat16 g_zh [NN*256];
__device__ __nv_bfloat16 g_zl [NN*256];
__device__ __nv_bfloat16 g_th [NN*HD];
__device__ __nv_bfloat16 g_tl [NN*HD];
__device__ __nv_bfloat16 g_wth[WTOT];
__device__ __nv_bfloat16 g_wtl[WTOT];

// ---------------- helpers ----------------
__device__ __forceinline__ uint32_t smem_u32(const void* p) {
    uint32_t a;
    asm("{ .reg .u64 t; cvta.to.shared.u64 t, %1; cvt.u32.u64 %0, t; }" : "=r"(a) : "l"(p));
    return a;
}
__device__ __forceinline__ void cp16(uint32_t s, const void* g, int sz) {
    asm volatile("cp.async.cg.shared.global [%0], [%1], 16, %2;"
                 :: "r"(s), "l"(g), "r"(sz));
}
#define LDSM4(R, addr) \
    asm volatile("ldmatrix.sync.aligned.m8n8.x4.shared.b16 {%0,%1,%2,%3}, [%4];" \
        : "=r"((R)[0]), "=r"((R)[1]), "=r"((R)[2]), "=r"((R)[3]) : "r"(addr))

__device__ __forceinline__ void mma16816(float* d, const uint32_t* a,
                                         uint32_t b0, uint32_t b1) {
    asm volatile("mma.sync.aligned.m16n8k16.row.col.f32.bf16.bf16.f32 "
        "{%0,%1,%2,%3}, {%4,%5,%6,%7}, {%8,%9}, {%0,%1,%2,%3};"
        : "+f"(d[0]), "+f"(d[1]), "+f"(d[2]), "+f"(d[3])
        : "r"(a[0]), "r"(a[1]), "r"(a[2]), "r"(a[3]), "r"(b0), "r"(b1));
}

__device__ __forceinline__ float gelu_f(float x) {
    return 0.5f * x * (1.0f + erff(x * 0.70710678118654752f));
}
__device__ __forceinline__ void split_bf16(float v, __nv_bfloat16& h, __nv_bfloat16& l) {
    h = __float2bfloat16(v);
    l = __float2bfloat16(v - __bfloat162float(h));
}

// ---------------- tiny utility kernels ----------------
__global__ void zero_int_kernel(int* p, int n) {
    int i = blockIdx.x * blockDim.x + threadIdx.x;
    if (i < n) p[i] = 0;
}
__global__ void zero_float_kernel(float* p, int n) {
    int i = blockIdx.x * blockDim.x + threadIdx.x;
    if (i < n) p[i] = 0.0f;
}
__global__ void aux_kernel(const float* __restrict__ aux, const float* __restrict__ c,
                           const float* __restrict__ d, float* __restrict__ out) {
    int i = blockIdx.x * blockDim.x + threadIdx.x;
    if (i < NN) {
        float v = c[0] * aux[i] - d[0];
        out[i] = 1.0f / (1.0f + __expf(-v));
    }
}
__global__ void hist_kernel(const int* __restrict__ ei, int* __restrict__ din,
                            int* __restrict__ dout) {
    int e = blockIdx.x * blockDim.x + threadIdx.x;
    if (e >= EE) return;
    int s = ei[e];
    int d = ei[EE + e];
    atomicAdd(&dout[s], 1);
    atomicAdd(&din[d], 1);
}
// fast single-block scan: per-thread serial chunk + block scan of partials
__global__ void scan_kernel(const int* __restrict__ deg, int* __restrict__ roff,
                            int* __restrict__ cursor, int* __restrict__ colidx) {
    __shared__ int sh[1024];
    const int CH = (NN + 1023) / 1024;
    int t = threadIdx.x;
    int s0 = t * CH;
    int s1 = min(s0 + CH, NN);
    int sum = 0;
    for (int i = s0; i < s1; ++i) sum += deg[i] + 1;
    sh[t] = sum;
    __syncthreads();
    for (int off = 1; off < 1024; off <<= 1) {
        int v = (t >= off) ? sh[t - off] : 0;
        __syncthreads();
        sh[t] += v;
        __syncthreads();
    }
    int run = sh[t] - sum;
    if (t == 0) roff[0] = 0;
    for (int i = s0; i < s1; ++i) {
        int v = deg[i] + 1;
        colidx[run] = i;       // self loop first
        cursor[i] = run + 1;
        run += v;
        roff[i + 1] = run;
    }
}
__global__ void scatter_kernel(const int* __restrict__ ei, int* __restrict__ cin,
                               int* __restrict__ colin, int* __restrict__ cout,
                               int* __restrict__ colout) {
    int e = blockIdx.x * blockDim.x + threadIdx.x;
    if (e >= EE) return;
    int s = ei[e];
    int d = ei[EE + e];
    int p = atomicAdd(&cin[d], 1);  colin[p]  = s;
    int q = atomicAdd(&cout[s], 1); colout[q] = d;
}

// ---------------- batchnorm ----------------
__global__ void bn_reduce_kernel(const float* __restrict__ h, float* __restrict__ stat) {
    int col = threadIdx.x;
    float s = 0.f, ss = 0.f;
    for (int r = blockIdx.x; r < NN; r += gridDim.x) {
        float v = h[(size_t)r * HD + col];
        s += v; ss += v * v;
    }
    atomicAdd(&stat[col], s);
    atomicAdd(&stat[128 + col], ss);
}
__global__ void bn_apply_kernel(const float* __restrict__ h, const float* __restrict__ stat,
                                const float* __restrict__ gamma, const float* __restrict__ beta,
                                __nv_bfloat16* __restrict__ hh, __nv_bfloat16* __restrict__ hl) {
    int idx = blockIdx.x * blockDim.x + threadIdx.x;
    if (idx >= NN * HD) return;
    int col = idx & (HD - 1);
    const float invN = 1.0f / (float)NN;
    float mu  = stat[col] * invN;
    float var = stat[128 + col] * invN - mu * mu;
    float v = (h[idx] - mu) * rsqrtf(var + 1e-5f) * gamma[col] + beta[col];
    __nv_bfloat16 a, b; split_bf16(v, a, b);
    hh[idx] = a; hl[idx] = b;
}

// ---------------- row inverse-norm ----------------
__global__ void invnorm_kernel(const float* __restrict__ x, float* __restrict__ invn) {
    int w = (blockIdx.x * blockDim.x + threadIdx.x) >> 5;
    int lane = threadIdx.x & 31;
    if (w >= NN) return;
    float4 v = *(const float4*)&x[(size_t)w * HD + lane * 4];
    float ss = v.x * v.x + v.y * v.y + v.z * v.z + v.w * v.w;
    ss += __shfl_xor_sync(0xffffffffu, ss, 16);
    ss += __shfl_xor_sync(0xffffffffu, ss, 8);
    ss += __shfl_xor_sync(0xffffffffu, ss, 4);
    ss += __shfl_xor_sync(0xffffffffu, ss, 2);
    ss += __shfl_xor_sync(0xffffffffu, ss, 1);
    if (lane == 0) invn[w] = 1.0f / fmaxf(sqrtf(ss), 1e-12f);
}

// ---------------- bias @ wcat fold ----------------
__global__ void bvec_kernel(const float* __restrict__ bias, const float* __restrict__ wcat,
                            float* __restrict__ bvec) {
    int tid = threadIdx.x;
    int dir = tid >> 7, t = tid & 127;
    const float* b = bias + dir * 128;
    const float* w = wcat + dir * 128 * 128;
    float acc = 0.f;
    for (int k = 0; k < 128; ++k) acc += b[k] * w[k * 128 + t];
    bvec[tid] = acc;
}

// ---------------- GAT-COS aggregation (warp per target node), bf16 hi/lo out ----
__global__ void gat_kernel(const int* __restrict__ roff, const int* __restrict__ col,
                           const float* __restrict__ xl, const float* __restrict__ xr,
                           const float* __restrict__ invl, const float* __restrict__ invr,
                           const float* __restrict__ xaux,
                           __nv_bfloat16* __restrict__ aggh, __nv_bfloat16* __restrict__ aggl) {
    int w = (blockIdx.x * blockDim.x + threadIdx.x) >> 5;
    int lane = threadIdx.x & 31;
    if (w >= NN) return;
    float inr = invr[w];
    float4 xri = *(const float4*)&xr[(size_t)w * HD + lane * 4];
    float4 nr = make_float4(xri.x * inr, xri.y * inr, xri.z * inr, xri.w * inr);
    float s = 0.f;
    float4 acc = make_float4(0.f, 0.f, 0.f, 0.f);
    int e0 = roff[w], e1 = roff[w + 1];
    for (int e = e0; e < e1; ++e) {
        int j = col[e];
        float4 xj = *(const float4*)&xl[(size_t)j * HD + lane * 4];
        float p = nr.x * xj.x + nr.y * xj.y + nr.z * xj.z + nr.w * xj.w;
        p += __shfl_xor_sync(0xffffffffu, p, 16);
        p += __shfl_xor_sync(0xffffffffu, p, 8);
        p += __shfl_xor_sync(0xffffffffu, p, 4);
        p += __shfl_xor_sync(0xffffffffu, p, 2);
        p += __shfl_xor_sync(0xffffffffu, p, 1);
        float a  = xaux[j] * fabsf(p) * invl[j] * 4.0f;
        float ee = __expf(a);
        s += ee;
        acc.x += ee * xj.x; acc.y += ee * xj.y;
        acc.z += ee * xj.z; acc.w += ee * xj.w;
    }
    float is = 1.0f / s;
    float o[4] = {acc.x * is, acc.y * is, acc.z * is, acc.w * is};
    size_t base = (size_t)w * HD + lane * 4;
    __nv_bfloat16 h0, l0, h1, l1, h2, l2, h3, l3;
    split_bf16(o[0], h0, l0); split_bf16(o[1], h1, l1);
    split_bf16(o[2], h2, l2); split_bf16(o[3], h3, l3);
    __nv_bfloat162 ha, hb, la, lb;
    ha.x = h0; ha.y = h1; hb.x = h2; hb.y = h3;
    la.x = l0; la.y = l1; lb.x = l2; lb.y = l3;
    *(__nv_bfloat162*)&aggh[base]     = ha;
    *(__nv_bfloat162*)&aggh[base + 2] = hb;
    *(__nv_bfloat162*)&aggl[base]     = la;
    *(__nv_bfloat162*)&aggl[base + 2] = lb;
}

// ---------------- input x -> bf16 hi/lo ----------------
__global__ void xconv_kernel(const float* __restrict__ x, __nv_bfloat16* __restrict__ xh,
                             __nv_bfloat16* __restrict__ xl, int n4) {
    int i = blockIdx.x * blockDim.x + threadIdx.x;
    if (i >= n4) return;
    float4 v = *(const float4*)&x[i * 4];
    __nv_bfloat16 h0, l0, h1, l1, h2, l2, h3, l3;
    split_bf16(v.x, h0, l0); split_bf16(v.y, h1, l1);
    split_bf16(v.z, h2, l2); split_bf16(v.w, h3, l3);
    __nv_bfloat162 ha, hb, la, lb;
    ha.x = h0; ha.y = h1; hb.x = h2; hb.y = h3;
    la.x = l0; la.y = l1; lb.x = l2; lb.y = l3;
    *(__nv_bfloat162*)&xh[i * 4]     = ha;
    *(__nv_bfloat162*)&xh[i * 4 + 2] = hb;
    *(__nv_bfloat162*)&xl[i * 4]     = la;
    *(__nv_bfloat162*)&xl[i * 4 + 2] = lb;
}

// ---------------- weight transpose + split: W[K,N] fp32 -> WT[N,K] bf16 hi/lo ---
struct WTab {
    const float* src[18];
    int K[18];
    int N[18];
    int off[18];
};
__global__ void wconv_kernel(WTab tb, __nv_bfloat16* __restrict__ wh,
                             __nv_bfloat16* __restrict__ wl) {
    int e = blockIdx.y;
    int i = blockIdx.x * 256 + threadIdx.x;
    int K = tb.K[e], N = tb.N[e];
    if (i >= K * N) return;
    int k = i / N, n = i - k * N;
    float w = tb.src[e][(size_t)k * N + n];
    __nv_bfloat16 h, l; split_bf16(w, h, l);
    size_t o = (size_t)tb.off[e] + (size_t)n * K + k;
    wh[o] = h; wl[o] = l;
}

// ---------------- HMMA GEMM: C[M,N'] = (Ah+Al)[M,K] @ (Bh+Bl)[N',K]^T ----------
// 3 K-sections: Ah*Bh + Al*Bh + Ah*Bl.  OMODE 0: fp32; 1: bf16 hi/lo; 2: both.
// CTA tile 128x128, 8 warps (warp tile 32x64), K-chunk 32, double-buffered.
#define SM_STRIDE 80            // padded row stride (bytes) -> conflict-free ldmatrix
#define BUF_BYTES 20480         // (128 rows A + 128 rows B) * 80
template<bool GELU, int OMODE>
__global__ void __launch_bounds__(256, 1)
hmma_kernel(const __nv_bfloat16* __restrict__ Ah, const __nv_bfloat16* __restrict__ Al,
            const __nv_bfloat16* __restrict__ Bh, const __nv_bfloat16* __restrict__ Bl,
            float* __restrict__ C, __nv_bfloat16* __restrict__ Ch,
            __nv_bfloat16* __restrict__ Cl, const float* __restrict__ bias,
            int M, int K, int ldc)
{
    __shared__ char smem[2 * BUF_BYTES];
    const uint32_t sbase = smem_u32(smem);
    const int tid = threadIdx.x, lane = tid & 31, wid = tid >> 5;
    const int warp_m = wid & 3, warp_n = wid >> 2;
    const int row0 = blockIdx.y * 128;
    const int col0 = blockIdx.x * 128;
    const int KB = K * 2;
    const int nkc = K >> 5;
    const int T = 3 * nkc;

    const char* pa[3] = {(const char*)Ah, (const char*)Al, (const char*)Ah};
    const char* pb[3] = {(const char*)Bh, (const char*)Bh, (const char*)Bl};

    float acc[2][8][4];
    #pragma unroll
    for (int i = 0; i < 2; ++i)
        #pragma unroll
        for (int j = 0; j < 8; ++j)
            #pragma unroll
            for (int k = 0; k < 4; ++k) acc[i][j][k] = 0.f;

    auto load = [&](int c, int b) {
        int s = c / nkc, in = c - s * nkc;
        const char* A0 = pa[s] + (size_t)row0 * KB + in * 64;
        const char* B0 = pb[s] + (size_t)col0 * KB + in * 64;
        uint32_t sA = sbase + b * BUF_BYTES;
        uint32_t sB = sA + 10240;
        #pragma unroll
        for (int i = 0; i < 2; ++i) {
            int g = tid + i * 256;           // 0..511
            int r = g >> 2, ch = g & 3;
            uint32_t so = r * SM_STRIDE + ch * 16;
            int sz = (row0 + r < M) ? 16 : 0;
            const char* ga = A0 + (size_t)(sz ? r : 0) * KB + ch * 16;
            cp16(sA + so, ga, sz);
            cp16(sB + so, B0 + (size_t)r * KB + ch * 16, 16);
        }
        asm volatile("cp.async.commit_group;" ::: "memory");
    };

    load(0, 0);

    for (int c = 0; c < T; ++c) {
        if (c + 1 < T) {
            load(c + 1, (c + 1) & 1);
            asm volatile("cp.async.wait_group 1;" ::: "memory");
        } else {
            asm volatile("cp.async.wait_group 0;" ::: "memory");
        }
        __syncthreads();

        uint32_t sA = sbase + (c & 1) * BUF_BYTES;
        uint32_t sB = sA + 10240;
        #pragma unroll
        for (int ks = 0; ks < 2; ++ks) {
            uint32_t a[2][4];
            #pragma unroll
            for (int fm = 0; fm < 2; ++fm) {
                int rr = warp_m * 32 + fm * 16 + (lane & 15);
                uint32_t ad = sA + rr * SM_STRIDE + ks * 32 + ((lane >> 4) << 4);
                LDSM4(a[fm], ad);
            }
            uint32_t bb[4][4];
            #pragma unroll
            for (int fb = 0; fb < 4; ++fb) {
                int rn = warp_n * 64 + fb * 16 + (lane & 7) + ((lane >> 4) << 3);
                uint32_t bd = sB + rn * SM_STRIDE + ks * 32 + (((lane >> 3) & 1) << 4);
                LDSM4(bb[fb], bd);
            }
            #pragma unroll
            for (int fm = 0; fm < 2; ++fm)
                #pragma unroll
                for (int fb = 0; fb < 4; ++fb) {
                    mma16816(acc[fm][fb * 2],     a[fm], bb[fb][0], bb[fb][1]);
                    mma16816(acc[fm][fb * 2 + 1], a[fm], bb[fb][2], bb[fb][3]);
                }
        }
        __syncthreads();
    }

    // epilogue
    #pragma unroll
    for (int fm = 0; fm < 2; ++fm) {
        int rbase = row0 + warp_m * 32 + fm * 16 + (lane >> 2);
        #pragma unroll
        for (int half = 0; half < 2; ++half) {
            int r = rbase + half * 8;
            if (r >= M) continue;
            #pragma unroll
            for (int fn = 0; fn < 8; ++fn) {
                int cc = col0 + warp_n * 64 + fn * 8 + (lane & 3) * 2;
                float v0 = acc[fm][fn][half * 2];
                float v1 = acc[fm][fn][half * 2 + 1];
                if (bias) { v0 += bias[cc]; v1 += bias[cc + 1]; }
                if (GELU) { v0 = gelu_f(v0); v1 = gelu_f(v1); }
                size_t o = (size_t)r * ldc + cc;
                if (OMODE == 0 || OMODE == 2) {
                    float2 f2 = make_float2(v0, v1);
                    *(float2*)&C[o] = f2;
                }
                if (OMODE == 1 || OMODE == 2) {
                    __nv_bfloat16 h0, l0, h1, l1;
                    split_bf16(v0, h0, l0); split_bf16(v1, h1, l1);
                    __nv_bfloat162 hp, lp;
                    hp.x = h0; hp.y = h1; lp.x = l0; lp.y = l1;
                    *(__nv_bfloat162*)&Ch[o] = hp;
                    *(__nv_bfloat162*)&Cl[o] = lp;
                }
            }
        }
    }
}

// ---------------- host ----------------
static void* sym(const void* s) {
    void* p = nullptr;
    cudaGetSymbolAddress(&p, s);
    return p;
}

extern "C" void kernel_launch(void* const* d_in, const int* in_sizes, int n_in,
                              void* d_out, int out_size) {
    const float* x      = (const float*)d_in[0];
    const int*   ei     = (const int*)  d_in[1];
    const float* nsa    = (const float*)d_in[2];
    const float* c_p    = (const float*)d_in[3];
    const float* d_p    = (const float*)d_in[4];
    const float* w_in   = (const float*)d_in[5];
    const float* b_in   = (const float*)d_in[6];
    const float* bn_g   = (const float*)d_in[7];
    const float* bn_b   = (const float*)d_in[8];
    const float* lin_l  = (const float*)d_in[9];
    const float* lin_r  = (const float*)d_in[10];
    const float* attb   = (const float*)d_in[11];
    const float* wcat   = (const float*)d_in[12];
    const float* ffw1   = (const float*)d_in[13];
    const float* ffb1   = (const float*)d_in[14];
    const float* ffw2   = (const float*)d_in[15];
    const float* ffb2   = (const float*)d_in[16];
    const float* wproj  = (const float*)d_in[17];
    const float* bproj  = (const float*)d_in[18];
    float* out = (float*)d_out;

    float* p_h    = (float*)sym(g_h);
    float* p_xl0  = (float*)sym(g_xl0);
    float* p_xr0  = (float*)sym(g_xr0);
    float* p_xl1  = (float*)sym(g_xl1);
    float* p_xr1  = (float*)sym(g_xr1);
    float* p_invn = (float*)sym(g_invn);
    float* p_xaux = (float*)sym(g_xaux);
    float* p_bvec = (float*)sym(g_bvec);
    float* p_bn   = (float*)sym(g_bnstat);
    int* p_din  = (int*)sym(g_deg_in);
    int* p_dout = (int*)sym(g_deg_out);
    int* p_oin  = (int*)sym(g_off_in);
    int* p_oout = (int*)sym(g_off_out);
    int* p_cin  = (int*)sym(g_cur_in);
    int* p_cout = (int*)sym(g_cur_out);
    int* p_colin  = (int*)sym(g_col_in);
    int* p_colout = (int*)sym(g_col_out);
    __nv_bfloat16* p_xh  = (__nv_bfloat16*)sym(g_xh);
    __nv_bfloat16* p_xlo = (__nv_bfloat16*)sym(g_xlo);
    __nv_bfloat16* p_hh  = (__nv_bfloat16*)sym(g_hh);
    __nv_bfloat16* p_hl  = (__nv_bfloat16*)sym(g_hl);
    __nv_bfloat16* p_aAh = (__nv_bfloat16*)sym(g_aAh);
    __nv_bfloat16* p_aAl = (__nv_bfloat16*)sym(g_aAl);
    __nv_bfloat16* p_aBh = (__nv_bfloat16*)sym(g_aBh);
    __nv_bfloat16* p_aBl = (__nv_bfloat16*)sym(g_aBl);
    __nv_bfloat16* p_zh  = (__nv_bfloat16*)sym(g_zh);
    __nv_bfloat16* p_zl  = (__nv_bfloat16*)sym(g_zl);
    __nv_bfloat16* p_th  = (__nv_bfloat16*)sym(g_th);
    __nv_bfloat16* p_tl  = (__nv_bfloat16*)sym(g_tl);
    __nv_bfloat16* p_wth = (__nv_bfloat16*)sym(g_wth);
    __nv_bfloat16* p_wtl = (__nv_bfloat16*)sym(g_wtl);

    // ---- gating + CSR build ----
    aux_kernel<<<(NN + 255) / 256, 256>>>(nsa, c_p, d_p, p_xaux);
    zero_int_kernel<<<(NN + 255) / 256, 256>>>(p_din, NN);
    zero_int_kernel<<<(NN + 255) / 256, 256>>>(p_dout, NN);
    hist_kernel<<<(EE + 255) / 256, 256>>>(ei, p_din, p_dout);
    scan_kernel<<<1, 1024>>>(p_din, p_oin, p_cin, p_colin);
    scan_kernel<<<1, 1024>>>(p_dout, p_oout, p_cout, p_colout);
    scatter_kernel<<<(EE + 255) / 256, 256>>>(ei, p_cin, p_colin, p_cout, p_colout);

    // ---- operand conversions ----
    xconv_kernel<<<(NN * 256 / 4 + 255) / 256, 256>>>(x, p_xh, p_xlo, NN * 256 / 4);
    WTab tb;
    int e = 0;
    tb.src[e] = w_in; tb.K[e] = 256; tb.N[e] = 128; tb.off[e] = OFF_WIN; ++e;
    for (int i = 0; i < 4; ++i) { tb.src[e] = lin_l + (size_t)i * 16384; tb.K[e] = 128; tb.N[e] = 128; tb.off[e] = OFF_LL + i * 16384; ++e; }
    for (int i = 0; i < 4; ++i) { tb.src[e] = lin_r + (size_t)i * 16384; tb.K[e] = 128; tb.N[e] = 128; tb.off[e] = OFF_LR + i * 16384; ++e; }
    for (int i = 0; i < 4; ++i) { tb.src[e] = wcat + (size_t)i * 16384; tb.K[e] = 128; tb.N[e] = 128; tb.off[e] = OFF_WC + i * 16384; ++e; }
    for (int i = 0; i < 2; ++i) { tb.src[e] = ffw1 + (size_t)i * 32768; tb.K[e] = 256; tb.N[e] = 128; tb.off[e] = OFF_F1 + i * 32768; ++e; }
    for (int i = 0; i < 2; ++i) { tb.src[e] = ffw2 + (size_t)i * 16384; tb.K[e] = 128; tb.N[e] = 128; tb.off[e] = OFF_F2 + i * 16384; ++e; }
    tb.src[e] = wproj; tb.K[e] = 128; tb.N[e] = 512; tb.off[e] = OFF_PJ; ++e;
    wconv_kernel<<<dim3(256, 18), 256>>>(tb, p_wth, p_wtl);

    const int MB = (NN + 127) / 128;   // 391
    dim3 g1(1, MB), g4(4, MB);
    const int gatBlocks = (NN * 32 + 255) / 256;

    // ---- input projection: h = x @ w_in + b_in ----
    hmma_kernel<false, 0><<<g1, 256>>>(p_xh, p_xlo, p_wth + OFF_WIN, p_wtl + OFF_WIN,
                                       p_h, nullptr, nullptr, b_in, NN, 256, HD);

    for (int l = 0; l < 2; ++l) {
        zero_float_kernel<<<1, 256>>>(p_bn, 256);
        bn_reduce_kernel<<<512, 128>>>(p_h, p_bn);
        bn_apply_kernel<<<(NN * HD + 255) / 256, 256>>>(p_h, p_bn, bn_g + l * HD, bn_b + l * HD,
                                                        p_hh, p_hl);
        int i0 = l * 2, i1 = l * 2 + 1;
        hmma_kernel<false, 0><<<g1, 256>>>(p_hh, p_hl, p_wth + OFF_LL + i0 * 16384,
            p_wtl + OFF_LL + i0 * 16384, p_xl0, nullptr, nullptr, nullptr, NN, 128, HD);
        hmma_kernel<false, 0><<<g1, 256>>>(p_hh, p_hl, p_wth + OFF_LR + i0 * 16384,
            p_wtl + OFF_LR + i0 * 16384, p_xr0, nullptr, nullptr, nullptr, NN, 128, HD);
        hmma_kernel<false, 0><<<g1, 256>>>(p_hh, p_hl, p_wth + OFF_LL + i1 * 16384,
            p_wtl + OFF_LL + i1 * 16384, p_xl1, nullptr, nullptr, nullptr, NN, 128, HD);
        hmma_kernel<false, 0><<<g1, 256>>>(p_hh, p_hl, p_wth + OFF_LR + i1 * 16384,
            p_wtl + OFF_LR + i1 * 16384, p_xr1, nullptr, nullptr, nullptr, NN, 128, HD);

        invnorm_kernel<<<gatBlocks, 256>>>(p_xl0, p_invn + 0 * NN);
        invnorm_kernel<<<gatBlocks, 256>>>(p_xr0, p_invn + 1 * NN);
        invnorm_kernel<<<gatBlocks, 256>>>(p_xl1, p_invn + 2 * NN);
        invnorm_kernel<<<gatBlocks, 256>>>(p_xr1, p_invn + 3 * NN);

        bvec_kernel<<<1, 256>>>(attb + (size_t)l * 256, wcat + (size_t)l * 2 * HD * HD, p_bvec);

        gat_kernel<<<gatBlocks, 256>>>(p_oin, p_colin, p_xl0, p_xr0,
                                       p_invn + 0 * NN, p_invn + 1 * NN, p_xaux, p_aAh, p_aAl);
        gat_kernel<<<gatBlocks, 256>>>(p_oout, p_colout, p_xl1, p_xr1,
                                       p_invn + 2 * NN, p_invn + 3 * NN, p_xaux, p_aBh, p_aBl);

        // z = [gelu(aggA@wcat0 + b0) | gelu(aggB@wcat1 + b1)]  -> bf16 hi/lo, ldc=256
        hmma_kernel<true, 1><<<g1, 256>>>(p_aAh, p_aAl, p_wth + OFF_WC + i0 * 16384,
            p_wtl + OFF_WC + i0 * 16384, nullptr, p_zh, p_zl, p_bvec, NN, 128, 256);
        hmma_kernel<true, 1><<<g1, 256>>>(p_aBh, p_aBl, p_wth + OFF_WC + i1 * 16384,
            p_wtl + OFF_WC + i1 * 16384, nullptr, p_zh + 128, p_zl + 128, p_bvec + 128, NN, 128, 256);

        // ffn
        hmma_kernel<true, 1><<<g1, 256>>>(p_zh, p_zl, p_wth + OFF_F1 + l * 32768,
            p_wtl + OFF_F1 + l * 32768, nullptr, p_th, p_tl, ffb1 + l * HD, NN, 256, HD);
        hmma_kernel<false, 2><<<g1, 256>>>(p_th, p_tl, p_wth + OFF_F2 + l * 16384,
            p_wtl + OFF_F2 + l * 16384, p_h, p_hh, p_hl, ffb2 + l * HD, NN, 128, HD);
    }

    // final projection -> d_out [NN, 512]
    hmma_kernel<false, 0><<<g4, 256>>>(p_hh, p_hl, p_wth + OFF_PJ, p_wtl + OFF_PJ,
                                       out, nullptr, nullptr, bproj, NN, 128, 512);
}

// round 4
// speedup vs baseline: 1.7194x; 1.2417x over previous
#include <cuda_runtime.h>
#include <cuda_bf16.h>
#include <cstdint>
#include <math.h>

#define NN  50000
#define EE  800000
#define ET  850000
#define HD  128

// ---------------- weight-transpose offsets (elements) ----------------
#define OFF_WIN  0
#define OFF_PROJ 32768      // per layer: [wl0|wr0|wl1|wr1] each 16384, layer stride 65536
#define OFF_WC   163840
#define OFF_F1   229376
#define OFF_F2   294912
#define OFF_PJ   327680
#define WTOT     393216

// ---------------- device scratch ----------------
__device__ float g_h[NN*HD];
__device__ float g_x4[NN*512];      // fused projections: [xl0|xr0|xl1|xr1]
__device__ float g_invn[4*NN];      // even sections: xaux*4/norm ; odd: 1/norm
__device__ float g_xaux[NN];
__device__ float g_bvec[256];
__device__ float g_bnstat[256];
__device__ int   g_deg_in[NN];
__device__ int   g_deg_out[NN];
__device__ int   g_off_in[NN+1];
__device__ int   g_off_out[NN+1];
__device__ int   g_cur_in[NN];
__device__ int   g_cur_out[NN];
__device__ int   g_col_in[ET];
__device__ int   g_col_out[ET];
// bf16 hi/lo operand buffers
__device__ __nv_bfloat16 g_xh [NN*256];
__device__ __nv_bfloat16 g_xlo[NN*256];
__device__ __nv_bfloat16 g_hh [NN*HD];
__device__ __nv_bfloat16 g_hl [NN*HD];
__device__ __nv_bfloat16 g_aAh[NN*HD];
__device__ __nv_bfloat16 g_aAl[NN*HD];
__device__ __nv_bfloat16 g_aBh[NN*HD];
__device__ __nv_bfloat16 g_aBl[NN*HD];
__device__ __nv_bfloat16 g_zh [NN*256];
__device__ __nv_bfloat16 g_zl [NN*256];
__device__ __nv_bfloat16 g_th [NN*HD];
__device__ __nv_bfloat16 g_tl [NN*HD];
__device__ __nv_bfloat16 g_wth[WTOT];
__device__ __nv_bfloat16 g_wtl[WTOT];

// ---------------- helpers ----------------
__device__ __forceinline__ uint32_t smem_u32(const void* p) {
    uint32_t a;
    asm("{ .reg .u64 t; cvta.to.shared.u64 t, %1; cvt.u32.u64 %0, t; }" : "=r"(a) : "l"(p));
    return a;
}
__device__ __forceinline__ void cp16(uint32_t s, const void* g, int sz) {
    asm volatile("cp.async.cg.shared.global [%0], [%1], 16, %2;"
                 :: "r"(s), "l"(g), "r"(sz));
}
#define LDSM4(R, addr) \
    asm volatile("ldmatrix.sync.aligned.m8n8.x4.shared.b16 {%0,%1,%2,%3}, [%4];" \
        : "=r"((R)[0]), "=r"((R)[1]), "=r"((R)[2]), "=r"((R)[3]) : "r"(addr))

__device__ __forceinline__ void mma16816(float* d, const uint32_t* a,
                                         uint32_t b0, uint32_t b1) {
    asm volatile("mma.sync.aligned.m16n8k16.row.col.f32.bf16.bf16.f32 "
        "{%0,%1,%2,%3}, {%4,%5,%6,%7}, {%8,%9}, {%0,%1,%2,%3};"
        : "+f"(d[0]), "+f"(d[1]), "+f"(d[2]), "+f"(d[3])
        : "r"(a[0]), "r"(a[1]), "r"(a[2]), "r"(a[3]), "r"(b0), "r"(b1));
}

__device__ __forceinline__ float gelu_f(float x) {
    return 0.5f * x * (1.0f + erff(x * 0.70710678118654752f));
}
__device__ __forceinline__ void split_bf16(float v, __nv_bfloat16& h, __nv_bfloat16& l) {
    h = __float2bfloat16(v);
    l = __float2bfloat16(v - __bfloat162float(h));
}

// ---------------- tiny utility kernels ----------------
__global__ void zero_int_kernel(int* p, int n) {
    int i = blockIdx.x * blockDim.x + threadIdx.x;
    if (i < n) p[i] = 0;
}
__global__ void zero_float_kernel(float* p, int n) {
    int i = blockIdx.x * blockDim.x + threadIdx.x;
    if (i < n) p[i] = 0.0f;
}
__global__ void aux_kernel(const float* __restrict__ aux, const float* __restrict__ c,
                           const float* __restrict__ d, float* __restrict__ out) {
    int i = blockIdx.x * blockDim.x + threadIdx.x;
    if (i < NN) {
        float v = c[0] * aux[i] - d[0];
        out[i] = 1.0f / (1.0f + __expf(-v));
    }
}
__global__ void hist_kernel(const int* __restrict__ ei, int* __restrict__ din,
                            int* __restrict__ dout) {
    int e = blockIdx.x * blockDim.x + threadIdx.x;
    if (e >= EE) return;
    int s = ei[e];
    int d = ei[EE + e];
    atomicAdd(&dout[s], 1);
    atomicAdd(&din[d], 1);
}
__global__ void scan_kernel(const int* __restrict__ deg, int* __restrict__ roff,
                            int* __restrict__ cursor, int* __restrict__ colidx) {
    __shared__ int sh[1024];
    const int CH = (NN + 1023) / 1024;
    int t = threadIdx.x;
    int s0 = t * CH;
    int s1 = min(s0 + CH, NN);
    int sum = 0;
    for (int i = s0; i < s1; ++i) sum += deg[i] + 1;
    sh[t] = sum;
    __syncthreads();
    for (int off = 1; off < 1024; off <<= 1) {
        int v = (t >= off) ? sh[t - off] : 0;
        __syncthreads();
        sh[t] += v;
        __syncthreads();
    }
    int run = sh[t] - sum;
    if (t == 0) roff[0] = 0;
    for (int i = s0; i < s1; ++i) {
        int v = deg[i] + 1;
        colidx[run] = i;       // self loop first
        cursor[i] = run + 1;
        run += v;
        roff[i + 1] = run;
    }
}
__global__ void scatter_kernel(const int* __restrict__ ei, int* __restrict__ cin,
                               int* __restrict__ colin, int* __restrict__ cout,
                               int* __restrict__ colout) {
    int e = blockIdx.x * blockDim.x + threadIdx.x;
    if (e >= EE) return;
    int s = ei[e];
    int d = ei[EE + e];
    int p = atomicAdd(&cin[d], 1);  colin[p]  = s;
    int q = atomicAdd(&cout[s], 1); colout[q] = d;
}

// ---------------- batchnorm ----------------
__global__ void bn_reduce_kernel(const float* __restrict__ h, float* __restrict__ stat) {
    int col = threadIdx.x;
    float s = 0.f, ss = 0.f;
    for (int r = blockIdx.x; r < NN; r += gridDim.x) {
        float v = h[(size_t)r * HD + col];
        s += v; ss += v * v;
    }
    atomicAdd(&stat[col], s);
    atomicAdd(&stat[128 + col], ss);
}
__global__ void bn_apply_kernel(const float* __restrict__ h, const float* __restrict__ stat,
                                const float* __restrict__ gamma, const float* __restrict__ beta,
                                __nv_bfloat16* __restrict__ hh, __nv_bfloat16* __restrict__ hl) {
    int idx = blockIdx.x * blockDim.x + threadIdx.x;
    if (idx >= NN * HD) return;
    int col = idx & (HD - 1);
    const float invN = 1.0f / (float)NN;
    float mu  = stat[col] * invN;
    float var = stat[128 + col] * invN - mu * mu;
    float v = (h[idx] - mu) * rsqrtf(var + 1e-5f) * gamma[col] + beta[col];
    __nv_bfloat16 a, b; split_bf16(v, a, b);
    hh[idx] = a; hl[idx] = b;
}

// ---------------- fused 4-section inverse-norm (+gate fold) ----------------
// sec even (xl sides): out = xaux*4/norm ; sec odd (xr sides): out = 1/norm
__global__ void invnorm4_kernel(const float* __restrict__ x4, const float* __restrict__ xaux,
                                float* __restrict__ invn) {
    int w = (blockIdx.x * blockDim.x + threadIdx.x) >> 5;
    int lane = threadIdx.x & 31;
    if (w >= NN) return;
    const float* row = x4 + (size_t)w * 512;
    float ss[4];
    #pragma unroll
    for (int s = 0; s < 4; ++s) {
        float4 v = *(const float4*)&row[s * 128 + lane * 4];
        ss[s] = v.x * v.x + v.y * v.y + v.z * v.z + v.w * v.w;
    }
    #pragma unroll
    for (int off = 16; off > 0; off >>= 1) {
        ss[0] += __shfl_xor_sync(0xffffffffu, ss[0], off);
        ss[1] += __shfl_xor_sync(0xffffffffu, ss[1], off);
        ss[2] += __shfl_xor_sync(0xffffffffu, ss[2], off);
        ss[3] += __shfl_xor_sync(0xffffffffu, ss[3], off);
    }
    if (lane == 0) {
        float gw = xaux[w] * 4.0f;
        float i0 = 1.0f / fmaxf(sqrtf(ss[0]), 1e-12f);
        float i1 = 1.0f / fmaxf(sqrtf(ss[1]), 1e-12f);
        float i2 = 1.0f / fmaxf(sqrtf(ss[2]), 1e-12f);
        float i3 = 1.0f / fmaxf(sqrtf(ss[3]), 1e-12f);
        invn[0 * NN + w] = gw * i0;
        invn[1 * NN + w] = i1;
        invn[2 * NN + w] = gw * i2;
        invn[3 * NN + w] = i3;
    }
}

// ---------------- bias @ wcat fold ----------------
__global__ void bvec_kernel(const float* __restrict__ bias, const float* __restrict__ wcat,
                            float* __restrict__ bvec) {
    int tid = threadIdx.x;
    int dir = tid >> 7, t = tid & 127;
    const float* b = bias + dir * 128;
    const float* w = wcat + dir * 128 * 128;
    float acc = 0.f;
    for (int k = 0; k < 128; ++k) acc += b[k] * w[k * 128 + t];
    bvec[tid] = acc;
}

// ---------------- GAT-COS aggregation (warp per node, unroll x2) -------------
// gwl[j] already = xaux[j]*4/||xl_j|| ; inr = 1/||xr_i||
__global__ void gat_kernel(const int* __restrict__ roff, const int* __restrict__ col,
                           const float* __restrict__ xl, const float* __restrict__ xr,
                           const float* __restrict__ gwl, const float* __restrict__ invr,
                           __nv_bfloat16* __restrict__ aggh, __nv_bfloat16* __restrict__ aggl) {
    const int LD = 512;
    int w = (blockIdx.x * blockDim.x + threadIdx.x) >> 5;
    int lane = threadIdx.x & 31;
    if (w >= NN) return;
    float inr = invr[w];
    float4 xri = *(const float4*)&xr[(size_t)w * LD + lane * 4];
    float4 nr = make_float4(xri.x * inr, xri.y * inr, xri.z * inr, xri.w * inr);
    float s = 0.f;
    float4 acc = make_float4(0.f, 0.f, 0.f, 0.f);
    int e = roff[w], e1 = roff[w + 1];
    for (; e + 2 <= e1; e += 2) {
        int j0 = col[e], j1 = col[e + 1];
        float4 x0 = *(const float4*)&xl[(size_t)j0 * LD + lane * 4];
        float4 x1 = *(const float4*)&xl[(size_t)j1 * LD + lane * 4];
        float g0 = gwl[j0], g1 = gwl[j1];
        float p0 = nr.x * x0.x + nr.y * x0.y + nr.z * x0.z + nr.w * x0.w;
        float p1 = nr.x * x1.x + nr.y * x1.y + nr.z * x1.z + nr.w * x1.w;
        #pragma unroll
        for (int off = 16; off > 0; off >>= 1) {
            p0 += __shfl_xor_sync(0xffffffffu, p0, off);
            p1 += __shfl_xor_sync(0xffffffffu, p1, off);
        }
        float q0 = __expf(g0 * fabsf(p0));
        float q1 = __expf(g1 * fabsf(p1));
        s += q0 + q1;
        acc.x += q0 * x0.x + q1 * x1.x;
        acc.y += q0 * x0.y + q1 * x1.y;
        acc.z += q0 * x0.z + q1 * x1.z;
        acc.w += q0 * x0.w + q1 * x1.w;
    }
    if (e < e1) {
        int j0 = col[e];
        float4 x0 = *(const float4*)&xl[(size_t)j0 * LD + lane * 4];
        float g0 = gwl[j0];
        float p0 = nr.x * x0.x + nr.y * x0.y + nr.z * x0.z + nr.w * x0.w;
        #pragma unroll
        for (int off = 16; off > 0; off >>= 1)
            p0 += __shfl_xor_sync(0xffffffffu, p0, off);
        float q0 = __expf(g0 * fabsf(p0));
        s += q0;
        acc.x += q0 * x0.x; acc.y += q0 * x0.y;
        acc.z += q0 * x0.z; acc.w += q0 * x0.w;
    }
    float is = 1.0f / s;
    float o[4] = {acc.x * is, acc.y * is, acc.z * is, acc.w * is};
    size_t base = (size_t)w * HD + lane * 4;
    __nv_bfloat16 h0, l0, h1, l1, h2, l2, h3, l3;
    split_bf16(o[0], h0, l0); split_bf16(o[1], h1, l1);
    split_bf16(o[2], h2, l2); split_bf16(o[3], h3, l3);
    __nv_bfloat162 ha, hb, la, lb;
    ha.x = h0; ha.y = h1; hb.x = h2; hb.y = h3;
    la.x = l0; la.y = l1; lb.x = l2; lb.y = l3;
    *(__nv_bfloat162*)&aggh[base]     = ha;
    *(__nv_bfloat162*)&aggh[base + 2] = hb;
    *(__nv_bfloat162*)&aggl[base]     = la;
    *(__nv_bfloat162*)&aggl[base + 2] = lb;
}

// ---------------- input x -> bf16 hi/lo ----------------
__global__ void xconv_kernel(const float* __restrict__ x, __nv_bfloat16* __restrict__ xh,
                             __nv_bfloat16* __restrict__ xl, int n4) {
    int i = blockIdx.x * blockDim.x + threadIdx.x;
    if (i >= n4) return;
    float4 v = *(const float4*)&x[i * 4];
    __nv_bfloat16 h0, l0, h1, l1, h2, l2, h3, l3;
    split_bf16(v.x, h0, l0); split_bf16(v.y, h1, l1);
    split_bf16(v.z, h2, l2); split_bf16(v.w, h3, l3);
    __nv_bfloat162 ha, hb, la, lb;
    ha.x = h0; ha.y = h1; hb.x = h2; hb.y = h3;
    la.x = l0; la.y = l1; lb.x = l2; lb.y = l3;
    *(__nv_bfloat162*)&xh[i * 4]     = ha;
    *(__nv_bfloat162*)&xh[i * 4 + 2] = hb;
    *(__nv_bfloat162*)&xl[i * 4]     = la;
    *(__nv_bfloat162*)&xl[i * 4 + 2] = lb;
}

// ---------------- weight transpose + split ----------------
struct WTab {
    const float* src[18];
    int K[18];
    int N[18];
    int off[18];
};
__global__ void wconv_kernel(WTab tb, __nv_bfloat16* __restrict__ wh,
                             __nv_bfloat16* __restrict__ wl) {
    int e = blockIdx.y;
    int i = blockIdx.x * 256 + threadIdx.x;
    int K = tb.K[e], N = tb.N[e];
    if (i >= K * N) return;
    int k = i / N, n = i - k * N;
    float w = tb.src[e][(size_t)k * N + n];
    __nv_bfloat16 h, l; split_bf16(w, h, l);
    size_t o = (size_t)tb.off[e] + (size_t)n * K + k;
    wh[o] = h; wl[o] = l;
}

// ---------------- HMMA GEMM: C[M,N'] = (Ah+Al)[M,K] @ (Bh+Bl)[N',K]^T ----------
// 3 K-sections: Ah*Bh + Al*Bh + Ah*Bl.  OMODE 0: fp32; 1: bf16 hi/lo; 2: both.
// CTA tile 128x128, 8 warps, K-chunk 32, 3-stage cp.async pipeline.
#define SM_STRIDE 80
#define BUF_BYTES 20480
template<bool GELU, int OMODE>
__global__ void __launch_bounds__(256)
hmma_kernel(const __nv_bfloat16* __restrict__ Ah, const __nv_bfloat16* __restrict__ Al,
            const __nv_bfloat16* __restrict__ Bh, const __nv_bfloat16* __restrict__ Bl,
            float* __restrict__ C, __nv_bfloat16* __restrict__ Ch,
            __nv_bfloat16* __restrict__ Cl, const float* __restrict__ bias,
            int M, int K, int ldc)
{
    extern __shared__ char smem[];
    const uint32_t sbase = smem_u32(smem);
    const int tid = threadIdx.x, lane = tid & 31, wid = tid >> 5;
    const int warp_m = wid & 3, warp_n = wid >> 2;
    const int row0 = blockIdx.y * 128;
    const int col0 = blockIdx.x * 128;
    const int KB = K * 2;
    const int nkc = K >> 5;
    const int T = 3 * nkc;

    const char* pa[3] = {(const char*)Ah, (const char*)Al, (const char*)Ah};
    const char* pb[3] = {(const char*)Bh, (const char*)Bh, (const char*)Bl};

    float acc[2][8][4];
    #pragma unroll
    for (int i = 0; i < 2; ++i)
        #pragma unroll
        for (int j = 0; j < 8; ++j)
            #pragma unroll
            for (int k = 0; k < 4; ++k) acc[i][j][k] = 0.f;

    auto load = [&](int c, int b) {
        int s = c / nkc, in = c - s * nkc;
        const char* A0 = pa[s] + (size_t)row0 * KB + in * 64;
        const char* B0 = pb[s] + (size_t)col0 * KB + in * 64;
        uint32_t sA = sbase + b * BUF_BYTES;
        uint32_t sB = sA + 10240;
        #pragma unroll
        for (int i = 0; i < 2; ++i) {
            int g = tid + i * 256;
            int r = g >> 2, ch = g & 3;
            uint32_t so = r * SM_STRIDE + ch * 16;
            int sz = (row0 + r < M) ? 16 : 0;
            const char* ga = A0 + (size_t)(sz ? r : 0) * KB + ch * 16;
            cp16(sA + so, ga, sz);
            cp16(sB + so, B0 + (size_t)r * KB + ch * 16, 16);
        }
        asm volatile("cp.async.commit_group;" ::: "memory");
    };

    load(0, 0);
    if (T > 1) load(1, 1);

    for (int c = 0; c < T; ++c) {
        if (c + 2 < T) {
            load(c + 2, (c + 2) % 3);
            asm volatile("cp.async.wait_group 2;" ::: "memory");
        } else if (c + 1 < T) {
            asm volatile("cp.async.wait_group 1;" ::: "memory");
        } else {
            asm volatile("cp.async.wait_group 0;" ::: "memory");
        }
        __syncthreads();

        uint32_t sA = sbase + (c % 3) * BUF_BYTES;
        uint32_t sB = sA + 10240;
        #pragma unroll
        for (int ks = 0; ks < 2; ++ks) {
            uint32_t a[2][4];
            #pragma unroll
            for (int fm = 0; fm < 2; ++fm) {
                int rr = warp_m * 32 + fm * 16 + (lane & 15);
                uint32_t ad = sA + rr * SM_STRIDE + ks * 32 + ((lane >> 4) << 4);
                LDSM4(a[fm], ad);
            }
            uint32_t bb[4][4];
            #pragma unroll
            for (int fb = 0; fb < 4; ++fb) {
                int rn = warp_n * 64 + fb * 16 + (lane & 7) + ((lane >> 4) << 3);
                uint32_t bd = sB + rn * SM_STRIDE + ks * 32 + (((lane >> 3) & 1) << 4);
                LDSM4(bb[fb], bd);
            }
            #pragma unroll
            for (int fm = 0; fm < 2; ++fm)
                #pragma unroll
                for (int fb = 0; fb < 4; ++fb) {
                    mma16816(acc[fm][fb * 2],     a[fm], bb[fb][0], bb[fb][1]);
                    mma16816(acc[fm][fb * 2 + 1], a[fm], bb[fb][2], bb[fb][3]);
                }
        }
        __syncthreads();
    }

    // epilogue
    #pragma unroll
    for (int fm = 0; fm < 2; ++fm) {
        int rbase = row0 + warp_m * 32 + fm * 16 + (lane >> 2);
        #pragma unroll
        for (int half = 0; half < 2; ++half) {
            int r = rbase + half * 8;
            if (r >= M) continue;
            #pragma unroll
            for (int fn = 0; fn < 8; ++fn) {
                int cc = col0 + warp_n * 64 + fn * 8 + (lane & 3) * 2;
                float v0 = acc[fm][fn][half * 2];
                float v1 = acc[fm][fn][half * 2 + 1];
                if (bias) { v0 += bias[cc]; v1 += bias[cc + 1]; }
                if (GELU) { v0 = gelu_f(v0); v1 = gelu_f(v1); }
                size_t o = (size_t)r * ldc + cc;
                if (OMODE == 0 || OMODE == 2) {
                    float2 f2 = make_float2(v0, v1);
                    *(float2*)&C[o] = f2;
                }
                if (OMODE == 1 || OMODE == 2) {
                    __nv_bfloat16 h0, l0, h1, l1;
                    split_bf16(v0, h0, l0); split_bf16(v1, h1, l1);
                    __nv_bfloat162 hp, lp;
                    hp.x = h0; hp.y = h1; lp.x = l0; lp.y = l1;
                    *(__nv_bfloat162*)&Ch[o] = hp;
                    *(__nv_bfloat162*)&Cl[o] = lp;
                }
            }
        }
    }
}

// ---------------- host ----------------
static void* sym(const void* s) {
    void* p = nullptr;
    cudaGetSymbolAddress(&p, s);
    return p;
}

#define SMEM_HM (3 * BUF_BYTES)

extern "C" void kernel_launch(void* const* d_in, const int* in_sizes, int n_in,
                              void* d_out, int out_size) {
    const float* x      = (const float*)d_in[0];
    const int*   ei     = (const int*)  d_in[1];
    const float* nsa    = (const float*)d_in[2];
    const float* c_p    = (const float*)d_in[3];
    const float* d_p    = (const float*)d_in[4];
    const float* w_in   = (const float*)d_in[5];
    const float* b_in   = (const float*)d_in[6];
    const float* bn_g   = (const float*)d_in[7];
    const float* bn_b   = (const float*)d_in[8];
    const float* lin_l  = (const float*)d_in[9];
    const float* lin_r  = (const float*)d_in[10];
    const float* attb   = (const float*)d_in[11];
    const float* wcat   = (const float*)d_in[12];
    const float* ffw1   = (const float*)d_in[13];
    const float* ffb1   = (const float*)d_in[14];
    const float* ffw2   = (const float*)d_in[15];
    const float* ffb2   = (const float*)d_in[16];
    const float* wproj  = (const float*)d_in[17];
    const float* bproj  = (const float*)d_in[18];
    float* out = (float*)d_out;

    float* p_h    = (float*)sym(g_h);
    float* p_x4   = (float*)sym(g_x4);
    float* p_invn = (float*)sym(g_invn);
    float* p_xaux = (float*)sym(g_xaux);
    float* p_bvec = (float*)sym(g_bvec);
    float* p_bn   = (float*)sym(g_bnstat);
    int* p_din  = (int*)sym(g_deg_in);
    int* p_dout = (int*)sym(g_deg_out);
    int* p_oin  = (int*)sym(g_off_in);
    int* p_oout = (int*)sym(g_off_out);
    int* p_cin  = (int*)sym(g_cur_in);
    int* p_cout = (int*)sym(g_cur_out);
    int* p_colin  = (int*)sym(g_col_in);
    int* p_colout = (int*)sym(g_col_out);
    __nv_bfloat16* p_xh  = (__nv_bfloat16*)sym(g_xh);
    __nv_bfloat16* p_xlo = (__nv_bfloat16*)sym(g_xlo);
    __nv_bfloat16* p_hh  = (__nv_bfloat16*)sym(g_hh);
    __nv_bfloat16* p_hl  = (__nv_bfloat16*)sym(g_hl);
    __nv_bfloat16* p_aAh = (__nv_bfloat16*)sym(g_aAh);
    __nv_bfloat16* p_aAl = (__nv_bfloat16*)sym(g_aAl);
    __nv_bfloat16* p_aBh = (__nv_bfloat16*)sym(g_aBh);
    __nv_bfloat16* p_aBl = (__nv_bfloat16*)sym(g_aBl);
    __nv_bfloat16* p_zh  = (__nv_bfloat16*)sym(g_zh);
    __nv_bfloat16* p_zl  = (__nv_bfloat16*)sym(g_zl);
    __nv_bfloat16* p_th  = (__nv_bfloat16*)sym(g_th);
    __nv_bfloat16* p_tl  = (__nv_bfloat16*)sym(g_tl);
    __nv_bfloat16* p_wth = (__nv_bfloat16*)sym(g_wth);
    __nv_bfloat16* p_wtl = (__nv_bfloat16*)sym(g_wtl);

    cudaFuncSetAttribute(hmma_kernel<false, 0>, cudaFuncAttributeMaxDynamicSharedMemorySize, SMEM_HM);
    cudaFuncSetAttribute(hmma_kernel<true,  1>, cudaFuncAttributeMaxDynamicSharedMemorySize, SMEM_HM);
    cudaFuncSetAttribute(hmma_kernel<false, 2>, cudaFuncAttributeMaxDynamicSharedMemorySize, SMEM_HM);

    // ---- gating + CSR build ----
    aux_kernel<<<(NN + 255) / 256, 256>>>(nsa, c_p, d_p, p_xaux);
    zero_int_kernel<<<(NN + 255) / 256, 256>>>(p_din, NN);
    zero_int_kernel<<<(NN + 255) / 256, 256>>>(p_dout, NN);
    hist_kernel<<<(EE + 255) / 256, 256>>>(ei, p_din, p_dout);
    scan_kernel<<<1, 1024>>>(p_din, p_oin, p_cin, p_colin);
    scan_kernel<<<1, 1024>>>(p_dout, p_oout, p_cout, p_colout);
    scatter_kernel<<<(EE + 255) / 256, 256>>>(ei, p_cin, p_colin, p_cout, p_colout);

    // ---- operand conversions ----
    xconv_kernel<<<(NN * 256 / 4 + 255) / 256, 256>>>(x, p_xh, p_xlo, NN * 256 / 4);
    WTab tb;
    int e = 0;
    tb.src[e] = w_in; tb.K[e] = 256; tb.N[e] = 128; tb.off[e] = OFF_WIN; ++e;
    for (int l = 0; l < 2; ++l) {
        for (int d = 0; d < 2; ++d) {
            tb.src[e] = lin_l + (size_t)(l * 2 + d) * 16384; tb.K[e] = 128; tb.N[e] = 128;
            tb.off[e] = OFF_PROJ + l * 65536 + (d * 2 + 0) * 16384; ++e;
            tb.src[e] = lin_r + (size_t)(l * 2 + d) * 16384; tb.K[e] = 128; tb.N[e] = 128;
            tb.off[e] = OFF_PROJ + l * 65536 + (d * 2 + 1) * 16384; ++e;
        }
    }
    for (int i = 0; i < 4; ++i) { tb.src[e] = wcat + (size_t)i * 16384; tb.K[e] = 128; tb.N[e] = 128; tb.off[e] = OFF_WC + i * 16384; ++e; }
    for (int i = 0; i < 2; ++i) { tb.src[e] = ffw1 + (size_t)i * 32768; tb.K[e] = 256; tb.N[e] = 128; tb.off[e] = OFF_F1 + i * 32768; ++e; }
    for (int i = 0; i < 2; ++i) { tb.src[e] = ffw2 + (size_t)i * 16384; tb.K[e] = 128; tb.N[e] = 128; tb.off[e] = OFF_F2 + i * 16384; ++e; }
    tb.src[e] = wproj; tb.K[e] = 128; tb.N[e] = 512; tb.off[e] = OFF_PJ; ++e;
    wconv_kernel<<<dim3(256, 18), 256>>>(tb, p_wth, p_wtl);

    const int MB = (NN + 127) / 128;   // 391
    dim3 g1(1, MB), g4(4, MB);
    const int gatBlocks = (NN * 32 + 255) / 256;

    // ---- input projection: h = x @ w_in + b_in ----
    hmma_kernel<false, 0><<<g1, 256, SMEM_HM>>>(p_xh, p_xlo, p_wth + OFF_WIN, p_wtl + OFF_WIN,
                                                p_h, nullptr, nullptr, b_in, NN, 256, HD);

    for (int l = 0; l < 2; ++l) {
        zero_float_kernel<<<1, 256>>>(p_bn, 256);
        bn_reduce_kernel<<<512, 128>>>(p_h, p_bn);
        bn_apply_kernel<<<(NN * HD + 255) / 256, 256>>>(p_h, p_bn, bn_g + l * HD, bn_b + l * HD,
                                                        p_hh, p_hl);
        // fused projection: x4 = h @ [wl0|wr0|wl1|wr1]  (N=512)
        hmma_kernel<false, 0><<<g4, 256, SMEM_HM>>>(p_hh, p_hl,
            p_wth + OFF_PROJ + l * 65536, p_wtl + OFF_PROJ + l * 65536,
            p_x4, nullptr, nullptr, nullptr, NN, 128, 512);

        invnorm4_kernel<<<gatBlocks, 256>>>(p_x4, p_xaux, p_invn);

        bvec_kernel<<<1, 256>>>(attb + (size_t)l * 256, wcat + (size_t)l * 2 * HD * HD, p_bvec);

        // dir0: xl = cols[0:128], xr = cols[128:256]
        gat_kernel<<<gatBlocks, 256>>>(p_oin, p_colin, p_x4, p_x4 + 128,
                                       p_invn + 0 * NN, p_invn + 1 * NN, p_aAh, p_aAl);
        // dir1: xl = cols[256:384], xr = cols[384:512]
        gat_kernel<<<gatBlocks, 256>>>(p_oout, p_colout, p_x4 + 256, p_x4 + 384,
                                       p_invn + 2 * NN, p_invn + 3 * NN, p_aBh, p_aBl);

        int i0 = l * 2, i1 = l * 2 + 1;
        // z = [gelu(aggA@wcat0 + b0) | gelu(aggB@wcat1 + b1)]  -> bf16 hi/lo, ldc=256
        hmma_kernel<true, 1><<<g1, 256, SMEM_HM>>>(p_aAh, p_aAl, p_wth + OFF_WC + i0 * 16384,
            p_wtl + OFF_WC + i0 * 16384, nullptr, p_zh, p_zl, p_bvec, NN, 128, 256);
        hmma_kernel<true, 1><<<g1, 256, SMEM_HM>>>(p_aBh, p_aBl, p_wth + OFF_WC + i1 * 16384,
            p_wtl + OFF_WC + i1 * 16384, nullptr, p_zh + 128, p_zl + 128, p_bvec + 128, NN, 128, 256);

        // ffn
        hmma_kernel<true, 1><<<g1, 256, SMEM_HM>>>(p_zh, p_zl, p_wth + OFF_F1 + l * 32768,
            p_wtl + OFF_F1 + l * 32768, nullptr, p_th, p_tl, ffb1 + l * HD, NN, 256, HD);
        hmma_kernel<false, 2><<<g1, 256, SMEM_HM>>>(p_th, p_tl, p_wth + OFF_F2 + l * 16384,
            p_wtl + OFF_F2 + l * 16384, p_h, p_hh, p_hl, ffb2 + l * HD, NN, 128, HD);
    }

    // final projection -> d_out [NN, 512]
    hmma_kernel<false, 0><<<g4, 256, SMEM_HM>>>(p_hh, p_hl, p_wth + OFF_PJ, p_wtl + OFF_PJ,
                                                out, nullptr, nullptr, bproj, NN, 128, 512);
}